// round 3
// baseline (speedup 1.0000x reference)
#include <cuda_runtime.h>

#define BH_  16
#define SEQ  2048
#define HD   64
#define OUT_ELEMS (BH_*SEQ*HD)   // 2097152 floats; p_attn region follows

__device__ float g_rowsum[BH_ * SEQ];   // 32768 floats of scratch (static: allowed)

__global__ void zero_rs() {
    int i = blockIdx.x * 256 + threadIdx.x;
    if (i < BH_ * SEQ) g_rowsum[i] = 0.0f;
}

// ---------------------------------------------------------------------------
// Kernel A: S = Q K^T (128x128 tile), fused e = mask ? (p+1e-12)*exp(s/8) : 0
// writes unnormalized e into p_attn region, accumulates row sums.
// ---------------------------------------------------------------------------
__global__ __launch_bounds__(256, 2) void scores_k(
    const float* __restrict__ Q, const float* __restrict__ K,
    const int*  __restrict__ M, const float* __restrict__ P,
    float* __restrict__ E)
{
    __shared__ float Qs[8][128];
    __shared__ float Ks[8][128];
    const int bh = blockIdx.z;
    const int q0 = blockIdx.y * 128;
    const int k0 = blockIdx.x * 128;
    const int t  = threadIdx.x;
    const int tx = t & 15, ty = t >> 4;

    float acc[8][8];
#pragma unroll
    for (int i = 0; i < 8; i++)
#pragma unroll
        for (int j = 0; j < 8; j++) acc[i][j] = 0.0f;

    const float* Qb = Q + ((size_t)bh * SEQ + q0) * HD;
    const float* Kb = K + ((size_t)bh * SEQ + k0) * HD;
    const int lr = t >> 1;          // 0..127
    const int ld = (t & 1) * 4;     // 0 or 4 within 8-wide d-chunk

    for (int dc = 0; dc < 8; ++dc) {
        float4 qv = *(const float4*)(Qb + (size_t)lr * HD + dc * 8 + ld);
        float4 kv = *(const float4*)(Kb + (size_t)lr * HD + dc * 8 + ld);
        Qs[ld + 0][lr] = qv.x; Qs[ld + 1][lr] = qv.y;
        Qs[ld + 2][lr] = qv.z; Qs[ld + 3][lr] = qv.w;
        Ks[ld + 0][lr] = kv.x; Ks[ld + 1][lr] = kv.y;
        Ks[ld + 2][lr] = kv.z; Ks[ld + 3][lr] = kv.w;
        __syncthreads();
#pragma unroll
        for (int dd = 0; dd < 8; ++dd) {
            float a[8], b[8];
            float4 a0 = *(const float4*)&Qs[dd][ty * 4];
            float4 a1 = *(const float4*)&Qs[dd][64 + ty * 4];
            float4 b0 = *(const float4*)&Ks[dd][tx * 4];
            float4 b1 = *(const float4*)&Ks[dd][64 + tx * 4];
            a[0] = a0.x; a[1] = a0.y; a[2] = a0.z; a[3] = a0.w;
            a[4] = a1.x; a[5] = a1.y; a[6] = a1.z; a[7] = a1.w;
            b[0] = b0.x; b[1] = b0.y; b[2] = b0.z; b[3] = b0.w;
            b[4] = b1.x; b[5] = b1.y; b[6] = b1.z; b[7] = b1.w;
#pragma unroll
            for (int i = 0; i < 8; i++)
#pragma unroll
                for (int j = 0; j < 8; j++)
                    acc[i][j] += a[i] * b[j];
        }
        __syncthreads();
    }

    // Epilogue: e = mask ? (p+1e-12) * exp(s * 0.125) : 0 ; row sums
    const size_t mbase = ((size_t)bh * SEQ) * SEQ;
#pragma unroll
    for (int i = 0; i < 8; i++) {
        const int r = q0 + ty * 4 + (i & 3) + ((i >> 2) << 6);
        const size_t rowb = mbase + (size_t)r * SEQ + k0;
        float rs = 0.0f;
#pragma unroll
        for (int g = 0; g < 2; ++g) {
            const int c = tx * 4 + g * 64;
            int4   m4 = *(const int4*)  (M + rowb + c);
            float4 p4 = *(const float4*)(P + rowb + c);
            float4 e;
            e.x = m4.x ? (p4.x + 1e-12f) * __expf(acc[i][g * 4 + 0] * 0.125f) : 0.0f;
            e.y = m4.y ? (p4.y + 1e-12f) * __expf(acc[i][g * 4 + 1] * 0.125f) : 0.0f;
            e.z = m4.z ? (p4.z + 1e-12f) * __expf(acc[i][g * 4 + 2] * 0.125f) : 0.0f;
            e.w = m4.w ? (p4.w + 1e-12f) * __expf(acc[i][g * 4 + 3] * 0.125f) : 0.0f;
            *(float4*)(E + rowb + c) = e;
            rs += (e.x + e.y) + (e.z + e.w);
        }
        // reduce across the 16 tx-threads (they are a contiguous 16-lane group)
#pragma unroll
        for (int off = 8; off > 0; off >>= 1)
            rs += __shfl_down_sync(0xffffffffu, rs, off, 16);
        if (tx == 0) atomicAdd(&g_rowsum[bh * SEQ + r], rs);
    }
}

// ---------------------------------------------------------------------------
// Kernel B: out = (E * V) / rowsum   (256 q-rows x 64 d per CTA)
// ---------------------------------------------------------------------------
__global__ __launch_bounds__(256, 2) void pv_k(
    const float* __restrict__ E, const float* __restrict__ V,
    float* __restrict__ O)
{
    __shared__ float Es[8][256];
    __shared__ float Vs[8][64];
    const int bh = blockIdx.y;
    const int q0 = blockIdx.x * 256;
    const int t  = threadIdx.x;
    const int tx = t & 7, ty = t >> 3;   // tx: d-groups, ty: q-groups (0..31)

    float acc[8][8];
#pragma unroll
    for (int i = 0; i < 8; i++)
#pragma unroll
        for (int j = 0; j < 8; j++) acc[i][j] = 0.0f;

    const float* Eb = E + ((size_t)bh * SEQ + q0) * SEQ;
    const float* Vb = V + (size_t)bh * SEQ * HD;

    for (int kc = 0; kc < SEQ / 8; ++kc) {
        float4 e0 = *(const float4*)(Eb + (size_t)t * SEQ + kc * 8);
        float4 e1 = *(const float4*)(Eb + (size_t)t * SEQ + kc * 8 + 4);
        Es[0][t] = e0.x; Es[1][t] = e0.y; Es[2][t] = e0.z; Es[3][t] = e0.w;
        Es[4][t] = e1.x; Es[5][t] = e1.y; Es[6][t] = e1.z; Es[7][t] = e1.w;
        if (t < 128) {
            const int kk = t >> 4, d4 = (t & 15) * 4;
            float4 v = *(const float4*)(Vb + (size_t)(kc * 8 + kk) * HD + d4);
            *(float4*)&Vs[kk][d4] = v;
        }
        __syncthreads();
#pragma unroll
        for (int kk = 0; kk < 8; ++kk) {
            float a[8], b[8];
            float4 a0 = *(const float4*)&Es[kk][ty * 4];
            float4 a1 = *(const float4*)&Es[kk][128 + ty * 4];
            float4 b0 = *(const float4*)&Vs[kk][tx * 4];
            float4 b1 = *(const float4*)&Vs[kk][32 + tx * 4];
            a[0] = a0.x; a[1] = a0.y; a[2] = a0.z; a[3] = a0.w;
            a[4] = a1.x; a[5] = a1.y; a[6] = a1.z; a[7] = a1.w;
            b[0] = b0.x; b[1] = b0.y; b[2] = b0.z; b[3] = b0.w;
            b[4] = b1.x; b[5] = b1.y; b[6] = b1.z; b[7] = b1.w;
#pragma unroll
            for (int i = 0; i < 8; i++)
#pragma unroll
                for (int j = 0; j < 8; j++)
                    acc[i][j] += a[i] * b[j];
        }
        __syncthreads();
    }

#pragma unroll
    for (int i = 0; i < 8; i++) {
        const int r = q0 + ty * 4 + (i & 3) + ((i >> 2) << 7);
        const float inv = 1.0f / g_rowsum[bh * SEQ + r];
        const size_t ob = ((size_t)bh * SEQ + r) * HD;
#pragma unroll
        for (int g = 0; g < 2; ++g) {
            float4 o;
            o.x = acc[i][g * 4 + 0] * inv;
            o.y = acc[i][g * 4 + 1] * inv;
            o.z = acc[i][g * 4 + 2] * inv;
            o.w = acc[i][g * 4 + 3] * inv;
            *(float4*)(O + ob + tx * 4 + g * 32) = o;
        }
    }
}

// ---------------------------------------------------------------------------
// Kernel C: in-place normalize p_attn = E / rowsum
// ---------------------------------------------------------------------------
__global__ __launch_bounds__(256) void norm_k(float* __restrict__ E)
{
    const int row = blockIdx.x;             // 0..32767
    const float inv = 1.0f / g_rowsum[row];
    float4* p = (float4*)(E + (size_t)row * SEQ);
    const int i = threadIdx.x;
    float4 v0 = p[i];
    v0.x *= inv; v0.y *= inv; v0.z *= inv; v0.w *= inv;
    p[i] = v0;
    float4 v1 = p[i + 256];
    v1.x *= inv; v1.y *= inv; v1.z *= inv; v1.w *= inv;
    p[i + 256] = v1;
}

extern "C" void kernel_launch(void* const* d_in, const int* in_sizes, int n_in,
                              void* d_out, int out_size) {
    const float* Q = (const float*)d_in[0];
    const float* K = (const float*)d_in[1];
    const float* V = (const float*)d_in[2];
    const int*   M = (const int*)  d_in[3];
    const float* P = (const float*)d_in[4];
    float* out = (float*)d_out;
    float* E   = out + OUT_ELEMS;           // p_attn region

    zero_rs<<<(BH_ * SEQ + 255) / 256, 256>>>();
    scores_k<<<dim3(16, 16, BH_), 256>>>(Q, K, M, P, E);
    pv_k<<<dim3(SEQ / 256, BH_), 256>>>(E, V, out);
    norm_k<<<BH_ * SEQ, 256>>>(E);
}

// round 6
// speedup vs baseline: 1.3445x; 1.3445x over previous
#include <cuda_runtime.h>
#include <cuda_bf16.h>
#include <cstdint>

#define SEQ 2048
#define HD  64
#define OUT_ELEMS (16*SEQ*HD)

__device__ float g_rowsum[16 * SEQ];

// ---------------- helpers ----------------
__device__ __forceinline__ uint32_t smem_u32(const void* p) {
    uint32_t a;
    asm("{ .reg .u64 t; cvta.to.shared.u64 t, %1; cvt.u32.u64 %0, t; }" : "=r"(a) : "l"(p));
    return a;
}

#define LDSM4(r, a) \
    asm volatile("ldmatrix.sync.aligned.m8n8.x4.shared.b16 {%0,%1,%2,%3}, [%4];" \
        : "=r"((r)[0]), "=r"((r)[1]), "=r"((r)[2]), "=r"((r)[3]) : "r"(a))
#define LDSM2(r, a) \
    asm volatile("ldmatrix.sync.aligned.m8n8.x2.shared.b16 {%0,%1}, [%2];" \
        : "=r"((r)[0]), "=r"((r)[1]) : "r"(a))
#define LDSM2T(r, a) \
    asm volatile("ldmatrix.sync.aligned.m8n8.x2.trans.shared.b16 {%0,%1}, [%2];" \
        : "=r"((r)[0]), "=r"((r)[1]) : "r"(a))

__device__ __forceinline__ void mma16816(float* d, const uint32_t* a, const uint32_t* b) {
    asm volatile(
        "mma.sync.aligned.m16n8k16.row.col.f32.bf16.bf16.f32 "
        "{%0,%1,%2,%3}, {%4,%5,%6,%7}, {%8,%9}, {%0,%1,%2,%3};"
        : "+f"(d[0]), "+f"(d[1]), "+f"(d[2]), "+f"(d[3])
        : "r"(a[0]), "r"(a[1]), "r"(a[2]), "r"(a[3]), "r"(b[0]), "r"(b[1]));
}

// bf16 tiles: 64 elems (128B) per row, 16B-chunk xor swizzle
#define SW(o) ((o) ^ (((o) >> 3) & 0x70))
__device__ __forceinline__ uint32_t swz(uint32_t base, int row, int chunk) {
    return base + row * 128 + (((chunk ^ (row & 7)) & 7) << 4);
}

__device__ __forceinline__ void store_split4(float4 v, char* hb, char* lb, int off) {
    __nv_bfloat162 h0 = __floats2bfloat162_rn(v.x, v.y);
    __nv_bfloat162 h1 = __floats2bfloat162_rn(v.z, v.w);
    float2 f0 = __bfloat1622float2(h0), f1 = __bfloat1622float2(h1);
    __nv_bfloat162 l0 = __floats2bfloat162_rn(v.x - f0.x, v.y - f0.y);
    __nv_bfloat162 l1 = __floats2bfloat162_rn(v.z - f1.x, v.w - f1.y);
    int s0 = SW(off), s1 = SW(off + 4);
    *(uint32_t*)(hb + s0) = reinterpret_cast<uint32_t&>(h0);
    *(uint32_t*)(hb + s1) = reinterpret_cast<uint32_t&>(h1);
    *(uint32_t*)(lb + s0) = reinterpret_cast<uint32_t&>(l0);
    *(uint32_t*)(lb + s1) = reinterpret_cast<uint32_t&>(l1);
}

// ------------------- Kernel A: S=QK^T, exp epilogue, rowsum -------------------
// smem: QH 16K | QL 16K | KH 16K | KL 16K | stage 128x68 f32
#define A_QH 0
#define A_QL 16384
#define A_KH 32768
#define A_KL 49152
#define A_ST 65536
#define A_SZ (A_ST + 128*68*4)

__global__ void __launch_bounds__(256) scores_k(
    const float* __restrict__ Q, const float* __restrict__ Kg,
    const int* __restrict__ Mk, const float* __restrict__ P, float* __restrict__ E)
{
    extern __shared__ char sm[];
    const uint32_t sb = smem_u32(sm);
    const int t = threadIdx.x, w = t >> 5, lane = t & 31;
    const int mw = w >> 2, nw = w & 3;     // warp tile: rows mw*64, cols nw*32
    const int bh = blockIdx.y, q0 = blockIdx.x * 128;

    const float* Qb = Q + ((size_t)bh * SEQ + q0) * HD;
    const float* Kb = Kg + (size_t)bh * SEQ * HD;

#pragma unroll
    for (int i = 0; i < 8; i++) {
        int idx = t + i * 256, r = idx >> 4, c = idx & 15;
        store_split4(*(const float4*)(Qb + r * HD + c * 4), sm + A_QH, sm + A_QL, r * 128 + c * 8);
    }

    float* stg = (float*)(sm + A_ST);
    float rs[8];
#pragma unroll
    for (int i = 0; i < 8; i++) rs[i] = 0.0f;

    for (int kt = 0; kt < 16; kt++) {
        __syncthreads();
        const float* Kt = Kb + (size_t)kt * 128 * HD;
#pragma unroll
        for (int i = 0; i < 8; i++) {
            int idx = t + i * 256, r = idx >> 4, c = idx & 15;
            store_split4(*(const float4*)(Kt + r * HD + c * 4), sm + A_KH, sm + A_KL, r * 128 + c * 8);
        }
        __syncthreads();

        float acc[4][4][4];
#pragma unroll
        for (int mi = 0; mi < 4; mi++)
#pragma unroll
            for (int ni = 0; ni < 4; ni++)
#pragma unroll
                for (int j = 0; j < 4; j++) acc[mi][ni][j] = 0.0f;

#pragma unroll
        for (int kc = 0; kc < 4; kc++) {
            uint32_t bhf[4][2], blf[4][2];
#pragma unroll
            for (int ni = 0; ni < 4; ni++) {
                int nb = nw * 32 + ni * 8;
                uint32_t ad = swz(sb + A_KH, nb + (lane & 7), kc * 2 + ((lane >> 3) & 1));
                LDSM2(bhf[ni], ad);
                ad = swz(sb + A_KL, nb + (lane & 7), kc * 2 + ((lane >> 3) & 1));
                LDSM2(blf[ni], ad);
            }
#pragma unroll
            for (int mi = 0; mi < 4; mi++) {
                int mb = mw * 64 + mi * 16;
                uint32_t ah[4], al[4];
                uint32_t ad = swz(sb + A_QH, mb + (lane & 15), kc * 2 + (lane >> 4));
                LDSM4(ah, ad);
                ad = swz(sb + A_QL, mb + (lane & 15), kc * 2 + (lane >> 4));
                LDSM4(al, ad);
#pragma unroll
                for (int ni = 0; ni < 4; ni++) {
                    mma16816(acc[mi][ni], ah, bhf[ni]);
                    mma16816(acc[mi][ni], ah, blf[ni]);
                    mma16816(acc[mi][ni], al, bhf[ni]);
                }
            }
        }

        // two halves of 128x64 through the stage
#pragma unroll
        for (int h = 0; h < 2; h++) {
            if ((nw >> 1) == h) {
                int cb = (nw & 1) * 32 + 2 * (lane & 3);
                int r0 = mw * 64 + (lane >> 2);
#pragma unroll
                for (int mi = 0; mi < 4; mi++)
#pragma unroll
                    for (int ni = 0; ni < 4; ni++) {
                        float* s0 = &stg[(r0 + mi * 16) * 68 + cb + ni * 8];
                        *(float2*)s0 = make_float2(acc[mi][ni][0], acc[mi][ni][1]);
                        float* s1 = &stg[(r0 + mi * 16 + 8) * 68 + cb + ni * 8];
                        *(float2*)s1 = make_float2(acc[mi][ni][2], acc[mi][ni][3]);
                    }
            }
            __syncthreads();
#pragma unroll
            for (int i = 0; i < 8; i++) {
                int idx = t + i * 256, r = idx >> 4, c4 = idx & 15;
                float4 s4 = *(float4*)&stg[r * 68 + c4 * 4];
                size_t g = ((size_t)(bh * SEQ + q0 + r)) * SEQ + kt * 128 + h * 64 + c4 * 4;
                int4   m4 = *(const int4*)(Mk + g);
                float4 p4 = *(const float4*)(P + g);
                float4 e;
                e.x = m4.x ? (p4.x + 1e-12f) * __expf(s4.x * 0.125f) : 0.0f;
                e.y = m4.y ? (p4.y + 1e-12f) * __expf(s4.y * 0.125f) : 0.0f;
                e.z = m4.z ? (p4.z + 1e-12f) * __expf(s4.z * 0.125f) : 0.0f;
                e.w = m4.w ? (p4.w + 1e-12f) * __expf(s4.w * 0.125f) : 0.0f;
                *(float4*)(E + g) = e;
                rs[i] += (e.x + e.y) + (e.z + e.w);
            }
            __syncthreads();
        }
    }

#pragma unroll
    for (int i = 0; i < 8; i++) {
        float v = rs[i];
        v += __shfl_down_sync(0xffffffffu, v, 8, 16);
        v += __shfl_down_sync(0xffffffffu, v, 4, 16);
        v += __shfl_down_sync(0xffffffffu, v, 2, 16);
        v += __shfl_down_sync(0xffffffffu, v, 1, 16);
        if ((t & 15) == 0) g_rowsum[bh * SEQ + q0 + i * 16 + (t >> 4)] = v;
    }
}

// --------------- Kernel B: normalize E in place + O = p_attn V ---------------
// smem: EH 16K | EL 16K | VH 8K | VL 8K | inv 512B
#define B_EH 0
#define B_EL 16384
#define B_VH 32768
#define B_VL 40960
#define B_IV 49152
#define B_SZ (B_IV + 512)

__global__ void __launch_bounds__(256) pv_k(
    const float* __restrict__ Vg, float* __restrict__ E, float* __restrict__ O)
{
    extern __shared__ char sm[];
    const uint32_t sb = smem_u32(sm);
    const int t = threadIdx.x, w = t >> 5, lane = t & 31;
    const int mw = w >> 2, nw = w & 3;     // warp tile: rows mw*64, cols nw*16
    const int bh = blockIdx.y, q0 = blockIdx.x * 128;

    float* sinv = (float*)(sm + B_IV);
    if (t < 128) sinv[t] = 1.0f / g_rowsum[bh * SEQ + q0 + t];

    float* Eb = E + ((size_t)bh * SEQ + q0) * SEQ;
    const float* Vb = Vg + (size_t)bh * SEQ * HD;

    float acc[4][2][4];
#pragma unroll
    for (int mi = 0; mi < 4; mi++)
#pragma unroll
        for (int ni = 0; ni < 2; ni++)
#pragma unroll
            for (int j = 0; j < 4; j++) acc[mi][ni][j] = 0.0f;
    __syncthreads();

    for (int kt = 0; kt < 32; kt++) {
        // E tile 128x64: read, normalize, write back, split to smem
#pragma unroll
        for (int i = 0; i < 8; i++) {
            int idx = t + i * 256, r = idx >> 4, c = idx & 15;
            float* ga = Eb + (size_t)r * SEQ + kt * 64 + c * 4;
            float4 v = *(float4*)ga;
            float inv = sinv[r];
            v.x *= inv; v.y *= inv; v.z *= inv; v.w *= inv;
            *(float4*)ga = v;
            store_split4(v, sm + B_EH, sm + B_EL, r * 128 + c * 8);
        }
        // V tile 64x64 (natural [k][n])
#pragma unroll
        for (int i = 0; i < 4; i++) {
            int idx = t + i * 256, r = idx >> 4, c = idx & 15;
            float4 v = *(const float4*)(Vb + (size_t)(kt * 64 + r) * HD + c * 4);
            store_split4(v, sm + B_VH, sm + B_VL, r * 128 + c * 8);
        }
        __syncthreads();

#pragma unroll
        for (int kc = 0; kc < 4; kc++) {
            uint32_t bhf[2][2], blf[2][2];
#pragma unroll
            for (int ni = 0; ni < 2; ni++) {
                int nch = nw * 2 + ni;   // 16B chunk of n
                uint32_t ad = swz(sb + B_VH, kc * 16 + (lane & 15), nch);
                LDSM2T(bhf[ni], ad);
                ad = swz(sb + B_VL, kc * 16 + (lane & 15), nch);
                LDSM2T(blf[ni], ad);
            }
#pragma unroll
            for (int mi = 0; mi < 4; mi++) {
                int mb = mw * 64 + mi * 16;
                uint32_t ah[4], al[4];
                uint32_t ad = swz(sb + B_EH, mb + (lane & 15), kc * 2 + (lane >> 4));
                LDSM4(ah, ad);
                ad = swz(sb + B_EL, mb + (lane & 15), kc * 2 + (lane >> 4));
                LDSM4(al, ad);
#pragma unroll
                for (int ni = 0; ni < 2; ni++) {
                    mma16816(acc[mi][ni], ah, bhf[ni]);
                    mma16816(acc[mi][ni], ah, blf[ni]);
                    mma16816(acc[mi][ni], al, bhf[ni]);
                }
            }
        }
        __syncthreads();
    }

    // O direct from accumulators
    const int r0 = mw * 64 + (lane >> 2);
    const int c0 = nw * 16 + 2 * (lane & 3);
#pragma unroll
    for (int mi = 0; mi < 4; mi++)
#pragma unroll
        for (int ni = 0; ni < 2; ni++) {
            size_t g0 = ((size_t)(bh * SEQ + q0 + r0 + mi * 16)) * HD + c0 + ni * 8;
            *(float2*)(O + g0) = make_float2(acc[mi][ni][0], acc[mi][ni][1]);
            size_t g1 = g0 + 8 * HD;
            *(float2*)(O + g1) = make_float2(acc[mi][ni][2], acc[mi][ni][3]);
        }
}

extern "C" void kernel_launch(void* const* d_in, const int* in_sizes, int n_in,
                              void* d_out, int out_size) {
    const float* Q = (const float*)d_in[0];
    const float* K = (const float*)d_in[1];
    const float* V = (const float*)d_in[2];
    const int*   M = (const int*)  d_in[3];
    const float* P = (const float*)d_in[4];
    float* out = (float*)d_out;
    float* E   = out + OUT_ELEMS;

    cudaFuncSetAttribute(scores_k, cudaFuncAttributeMaxDynamicSharedMemorySize, A_SZ);
    cudaFuncSetAttribute(pv_k,     cudaFuncAttributeMaxDynamicSharedMemorySize, B_SZ);

    scores_k<<<dim3(16, 16), 256, A_SZ>>>(Q, K, M, P, E);
    pv_k<<<dim3(16, 16), 256, B_SZ>>>(V, E, out);
}

// round 7
// speedup vs baseline: 1.5819x; 1.1766x over previous
#include <cuda_runtime.h>
#include <cuda_bf16.h>
#include <cstdint>

#define SEQ 2048
#define HD  64
#define OUT_ELEMS (16*SEQ*HD)

__device__ float g_rowsum[16 * SEQ];

// ---------------- helpers ----------------
__device__ __forceinline__ uint32_t smem_u32(const void* p) {
    uint32_t a;
    asm("{ .reg .u64 t; cvta.to.shared.u64 t, %1; cvt.u32.u64 %0, t; }" : "=r"(a) : "l"(p));
    return a;
}

#define LDSM4(r, a) \
    asm volatile("ldmatrix.sync.aligned.m8n8.x4.shared.b16 {%0,%1,%2,%3}, [%4];" \
        : "=r"((r)[0]), "=r"((r)[1]), "=r"((r)[2]), "=r"((r)[3]) : "r"(a))
#define LDSM2(r, a) \
    asm volatile("ldmatrix.sync.aligned.m8n8.x2.shared.b16 {%0,%1}, [%2];" \
        : "=r"((r)[0]), "=r"((r)[1]) : "r"(a))
#define LDSM2T(r, a) \
    asm volatile("ldmatrix.sync.aligned.m8n8.x2.trans.shared.b16 {%0,%1}, [%2];" \
        : "=r"((r)[0]), "=r"((r)[1]) : "r"(a))

__device__ __forceinline__ void mma16816(float* d, const uint32_t* a, const uint32_t* b) {
    asm volatile(
        "mma.sync.aligned.m16n8k16.row.col.f32.bf16.bf16.f32 "
        "{%0,%1,%2,%3}, {%4,%5,%6,%7}, {%8,%9}, {%0,%1,%2,%3};"
        : "+f"(d[0]), "+f"(d[1]), "+f"(d[2]), "+f"(d[3])
        : "r"(a[0]), "r"(a[1]), "r"(a[2]), "r"(a[3]), "r"(b[0]), "r"(b[1]));
}

// fast 2^t : FFMA-only (no MUFU). |t| < 60 assumed.
__device__ __forceinline__ float fexp2(float t) {
    float z = t + 12582912.0f;               // round-to-nearest integer in low bits
    int   i = __float_as_int(z);
    float f = t - (z - 12582912.0f);         // f in [-0.5, 0.5]
    float p =          1.33335581e-3f;
    p = fmaf(p, f, 9.61812910e-3f);
    p = fmaf(p, f, 5.55041087e-2f);
    p = fmaf(p, f, 2.40226507e-1f);
    p = fmaf(p, f, 6.93147180e-1f);
    p = fmaf(p, f, 1.0f);
    float sc = __int_as_float((i + 127) << 23);
    return p * sc;
}
#define EXSCL 0.18033688011f   // 0.125 * log2(e)

// bf16 tiles: 64 elems (128B) per row, 16B-chunk xor swizzle
#define SW(o) ((o) ^ (((o) >> 3) & 0x70))
__device__ __forceinline__ uint32_t swz(uint32_t base, int row, int chunk) {
    return base + row * 128 + (((chunk ^ (row & 7)) & 7) << 4);
}

__device__ __forceinline__ void store_split4(float4 v, char* hb, char* lb, int off) {
    __nv_bfloat162 h0 = __floats2bfloat162_rn(v.x, v.y);
    __nv_bfloat162 h1 = __floats2bfloat162_rn(v.z, v.w);
    float2 f0 = __bfloat1622float2(h0), f1 = __bfloat1622float2(h1);
    __nv_bfloat162 l0 = __floats2bfloat162_rn(v.x - f0.x, v.y - f0.y);
    __nv_bfloat162 l1 = __floats2bfloat162_rn(v.z - f1.x, v.w - f1.y);
    int s0 = SW(off), s1 = SW(off + 4);
    *(uint32_t*)(hb + s0) = reinterpret_cast<uint32_t&>(h0);
    *(uint32_t*)(hb + s1) = reinterpret_cast<uint32_t&>(h1);
    *(uint32_t*)(lb + s0) = reinterpret_cast<uint32_t&>(l0);
    *(uint32_t*)(lb + s1) = reinterpret_cast<uint32_t&>(l1);
}

// ------------------- Kernel A: S=QK^T, exp epilogue, rowsum -------------------
// smem: QH 16K | QL 16K | KH 16K | KL 16K | stage 128x68 f32
#define A_QH 0
#define A_QL 16384
#define A_KH 32768
#define A_KL 49152
#define A_ST 65536
#define A_SZ (A_ST + 128*68*4)

__global__ void __launch_bounds__(256) scores_k(
    const float* __restrict__ Q, const float* __restrict__ Kg,
    const int* __restrict__ Mk, const float* __restrict__ P, float* __restrict__ E)
{
    extern __shared__ char sm[];
    const uint32_t sb = smem_u32(sm);
    const int t = threadIdx.x, w = t >> 5, lane = t & 31;
    const int mw = w >> 2, nw = w & 3;     // warp tile: rows mw*64, cols nw*32
    const int bh = blockIdx.y, q0 = blockIdx.x * 128;

    const float* Qb = Q + ((size_t)bh * SEQ + q0) * HD;
    const float* Kb = Kg + (size_t)bh * SEQ * HD;

#pragma unroll
    for (int i = 0; i < 8; i++) {
        int idx = t + i * 256, r = idx >> 4, c = idx & 15;
        store_split4(*(const float4*)(Qb + r * HD + c * 4), sm + A_QH, sm + A_QL, r * 128 + c * 8);
    }

    float* stg = (float*)(sm + A_ST);
    float rs[8];
#pragma unroll
    for (int i = 0; i < 8; i++) rs[i] = 0.0f;

    for (int kt = 0; kt < 16; kt++) {
        __syncthreads();
        const float* Kt = Kb + (size_t)kt * 128 * HD;
#pragma unroll
        for (int i = 0; i < 8; i++) {
            int idx = t + i * 256, r = idx >> 4, c = idx & 15;
            store_split4(*(const float4*)(Kt + r * HD + c * 4), sm + A_KH, sm + A_KL, r * 128 + c * 8);
        }
        __syncthreads();

        float acc[4][4][4];
#pragma unroll
        for (int mi = 0; mi < 4; mi++)
#pragma unroll
            for (int ni = 0; ni < 4; ni++)
#pragma unroll
                for (int j = 0; j < 4; j++) acc[mi][ni][j] = 0.0f;

#pragma unroll
        for (int kc = 0; kc < 4; kc++) {
            uint32_t bhf[4][2], blf[4][2];
#pragma unroll
            for (int ni = 0; ni < 4; ni++) {
                int nb = nw * 32 + ni * 8;
                uint32_t ad = swz(sb + A_KH, nb + (lane & 7), kc * 2 + ((lane >> 3) & 1));
                LDSM2(bhf[ni], ad);
                ad = swz(sb + A_KL, nb + (lane & 7), kc * 2 + ((lane >> 3) & 1));
                LDSM2(blf[ni], ad);
            }
#pragma unroll
            for (int mi = 0; mi < 4; mi++) {
                int mb = mw * 64 + mi * 16;
                uint32_t ah[4], al[4];
                uint32_t ad = swz(sb + A_QH, mb + (lane & 15), kc * 2 + (lane >> 4));
                LDSM4(ah, ad);
                ad = swz(sb + A_QL, mb + (lane & 15), kc * 2 + (lane >> 4));
                LDSM4(al, ad);
#pragma unroll
                for (int ni = 0; ni < 4; ni++) {
                    mma16816(acc[mi][ni], ah, bhf[ni]);
                    mma16816(acc[mi][ni], ah, blf[ni]);
                    mma16816(acc[mi][ni], al, bhf[ni]);
                }
            }
        }

        // two halves of 128x64 through the stage
#pragma unroll
        for (int h = 0; h < 2; h++) {
            if ((nw >> 1) == h) {
                int cb = (nw & 1) * 32 + 2 * (lane & 3);
                int r0 = mw * 64 + (lane >> 2);
#pragma unroll
                for (int mi = 0; mi < 4; mi++)
#pragma unroll
                    for (int ni = 0; ni < 4; ni++) {
                        float* s0 = &stg[(r0 + mi * 16) * 68 + cb + ni * 8];
                        *(float2*)s0 = make_float2(acc[mi][ni][0], acc[mi][ni][1]);
                        float* s1 = &stg[(r0 + mi * 16 + 8) * 68 + cb + ni * 8];
                        *(float2*)s1 = make_float2(acc[mi][ni][2], acc[mi][ni][3]);
                    }
            }
            __syncthreads();
#pragma unroll
            for (int i = 0; i < 8; i++) {
                int idx = t + i * 256, r = idx >> 4, c4 = idx & 15;
                float4 s4 = *(float4*)&stg[r * 68 + c4 * 4];
                size_t g = ((size_t)(bh * SEQ + q0 + r)) * SEQ + kt * 128 + h * 64 + c4 * 4;
                int4   m4 = *(const int4*)(Mk + g);
                float4 p4 = *(const float4*)(P + g);
                float4 e;
                e.x = m4.x ? (p4.x + 1e-12f) * fexp2(s4.x * EXSCL) : 0.0f;
                e.y = m4.y ? (p4.y + 1e-12f) * fexp2(s4.y * EXSCL) : 0.0f;
                e.z = m4.z ? (p4.z + 1e-12f) * fexp2(s4.z * EXSCL) : 0.0f;
                e.w = m4.w ? (p4.w + 1e-12f) * fexp2(s4.w * EXSCL) : 0.0f;
                *(float4*)(E + g) = e;
                rs[i] += (e.x + e.y) + (e.z + e.w);
            }
            __syncthreads();
        }
    }

#pragma unroll
    for (int i = 0; i < 8; i++) {
        float v = rs[i];
        v += __shfl_down_sync(0xffffffffu, v, 8, 16);
        v += __shfl_down_sync(0xffffffffu, v, 4, 16);
        v += __shfl_down_sync(0xffffffffu, v, 2, 16);
        v += __shfl_down_sync(0xffffffffu, v, 1, 16);
        if ((t & 15) == 0) g_rowsum[bh * SEQ + q0 + i * 16 + (t >> 4)] = v;
    }
}

// --------------- Kernel B: normalize E in place + O = p_attn V ---------------
// 64-row q-tiles, double-buffered smem, register prefetch.
// stage s (32KB): EH | EL | VH | VL (8KB each); inv 256B at end.
#define B_EH(s) ((s)*32768)
#define B_EL(s) ((s)*32768 + 8192)
#define B_VH(s) ((s)*32768 + 16384)
#define B_VL(s) ((s)*32768 + 24576)
#define B_IV 65536
#define B_SZ (B_IV + 256)

__global__ void __launch_bounds__(256) pv_k(
    const float* __restrict__ Vg, float* __restrict__ E, float* __restrict__ O)
{
    extern __shared__ char sm[];
    const uint32_t sb = smem_u32(sm);
    const int t = threadIdx.x, w = t >> 5, lane = t & 31;
    const int mw = w >> 1, nw = w & 1;     // warp tile: rows mw*16, cols nw*32
    const int bh = blockIdx.y, q0 = blockIdx.x * 64;

    float* sinv = (float*)(sm + B_IV);
    if (t < 64) sinv[t] = 1.0f / g_rowsum[bh * SEQ + q0 + t];

    float* Eb = E + ((size_t)bh * SEQ + q0) * SEQ;
    const float* Vb = Vg + (size_t)bh * SEQ * HD;

    const int r_ = t >> 4, c_ = t & 15;    // load mapping: rows r_+16i, col chunk c_

    float4 er[4], vr[4];
#pragma unroll
    for (int i = 0; i < 4; i++) {
        er[i] = *(const float4*)(Eb + (size_t)(r_ + i * 16) * SEQ + c_ * 4);
        vr[i] = *(const float4*)(Vb + (size_t)(r_ + i * 16) * HD + c_ * 4);
    }

    float acc[4][4];
#pragma unroll
    for (int ni = 0; ni < 4; ni++)
#pragma unroll
        for (int j = 0; j < 4; j++) acc[ni][j] = 0.0f;

    __syncthreads();   // sinv visible

    for (int kt = 0; kt < 32; kt++) {
        const int s = kt & 1;
        // normalize prefetched E, write back to global, split to smem
#pragma unroll
        for (int i = 0; i < 4; i++) {
            const int r = r_ + i * 16;
            const float inv = sinv[r];
            float4 v = er[i];
            v.x *= inv; v.y *= inv; v.z *= inv; v.w *= inv;
            *(float4*)(Eb + (size_t)r * SEQ + kt * 64 + c_ * 4) = v;
            store_split4(v, sm + B_EH(s), sm + B_EL(s), r * 128 + c_ * 8);
            store_split4(vr[i], sm + B_VH(s), sm + B_VL(s), r * 128 + c_ * 8);
        }
        __syncthreads();
        if (kt < 31) {   // prefetch next tiles; lands while MMA runs
#pragma unroll
            for (int i = 0; i < 4; i++) {
                er[i] = *(const float4*)(Eb + (size_t)(r_ + i * 16) * SEQ + (kt + 1) * 64 + c_ * 4);
                vr[i] = *(const float4*)(Vb + (size_t)((kt + 1) * 64 + r_ + i * 16) * HD + c_ * 4);
            }
        }
#pragma unroll
        for (int kc = 0; kc < 4; kc++) {
            uint32_t bhf[4][2], blf[4][2];
#pragma unroll
            for (int ni = 0; ni < 4; ni++) {
                const int nch = nw * 4 + ni;
                LDSM2T(bhf[ni], swz(sb + B_VH(s), kc * 16 + (lane & 15), nch));
                LDSM2T(blf[ni], swz(sb + B_VL(s), kc * 16 + (lane & 15), nch));
            }
            uint32_t ah[4], al[4];
            LDSM4(ah, swz(sb + B_EH(s), mw * 16 + (lane & 15), kc * 2 + (lane >> 4)));
            LDSM4(al, swz(sb + B_EL(s), mw * 16 + (lane & 15), kc * 2 + (lane >> 4)));
#pragma unroll
            for (int ni = 0; ni < 4; ni++) {
                mma16816(acc[ni], ah, bhf[ni]);
                mma16816(acc[ni], ah, blf[ni]);
                mma16816(acc[ni], al, bhf[ni]);
            }
        }
        // single barrier per iter: next writes go to the other stage; the
        // barrier at the next iteration orders reuse of this stage.
    }

    // O direct from accumulators
    const int r0 = mw * 16 + (lane >> 2);
    const int c0 = nw * 32 + 2 * (lane & 3);
#pragma unroll
    for (int ni = 0; ni < 4; ni++) {
        size_t g0 = ((size_t)(bh * SEQ + q0 + r0)) * HD + c0 + ni * 8;
        *(float2*)(O + g0) = make_float2(acc[ni][0], acc[ni][1]);
        *(float2*)(O + g0 + 8 * HD) = make_float2(acc[ni][2], acc[ni][3]);
    }
}

extern "C" void kernel_launch(void* const* d_in, const int* in_sizes, int n_in,
                              void* d_out, int out_size) {
    const float* Q = (const float*)d_in[0];
    const float* K = (const float*)d_in[1];
    const float* V = (const float*)d_in[2];
    const int*   M = (const int*)  d_in[3];
    const float* P = (const float*)d_in[4];
    float* out = (float*)d_out;
    float* E   = out + OUT_ELEMS;

    cudaFuncSetAttribute(scores_k, cudaFuncAttributeMaxDynamicSharedMemorySize, A_SZ);
    cudaFuncSetAttribute(pv_k,     cudaFuncAttributeMaxDynamicSharedMemorySize, B_SZ);

    scores_k<<<dim3(16, 16), 256, A_SZ>>>(Q, K, M, P, E);
    pv_k<<<dim3(32, 16), 256, B_SZ>>>(V, E, out);
}

// round 8
// speedup vs baseline: 2.2120x; 1.3983x over previous
#include <cuda_runtime.h>
#include <cuda_bf16.h>
#include <cstdint>

#define SEQ 2048
#define HD  64
#define OUT_ELEMS (16*SEQ*HD)

__device__ float g_rowsum[16 * SEQ];

// ---------------- helpers ----------------
__device__ __forceinline__ uint32_t smem_u32(const void* p) {
    uint32_t a;
    asm("{ .reg .u64 t; cvta.to.shared.u64 t, %1; cvt.u32.u64 %0, t; }" : "=r"(a) : "l"(p));
    return a;
}

#define LDSM4(r, a) \
    asm volatile("ldmatrix.sync.aligned.m8n8.x4.shared.b16 {%0,%1,%2,%3}, [%4];" \
        : "=r"((r)[0]), "=r"((r)[1]), "=r"((r)[2]), "=r"((r)[3]) : "r"(a))
#define LDSM2(r, a) \
    asm volatile("ldmatrix.sync.aligned.m8n8.x2.shared.b16 {%0,%1}, [%2];" \
        : "=r"((r)[0]), "=r"((r)[1]) : "r"(a))
#define LDSM2T(r, a) \
    asm volatile("ldmatrix.sync.aligned.m8n8.x2.trans.shared.b16 {%0,%1}, [%2];" \
        : "=r"((r)[0]), "=r"((r)[1]) : "r"(a))

__device__ __forceinline__ void mma16816(float* d, const uint32_t* a, const uint32_t* b) {
    asm volatile(
        "mma.sync.aligned.m16n8k16.row.col.f32.bf16.bf16.f32 "
        "{%0,%1,%2,%3}, {%4,%5,%6,%7}, {%8,%9}, {%0,%1,%2,%3};"
        : "+f"(d[0]), "+f"(d[1]), "+f"(d[2]), "+f"(d[3])
        : "r"(a[0]), "r"(a[1]), "r"(a[2]), "r"(a[3]), "r"(b[0]), "r"(b[1]));
}

// fast 2^t : FFMA-only. |t| < 60 assumed.
__device__ __forceinline__ float fexp2(float t) {
    float z = t + 12582912.0f;
    int   i = __float_as_int(z);
    float f = t - (z - 12582912.0f);
    float p =          1.33335581e-3f;
    p = fmaf(p, f, 9.61812910e-3f);
    p = fmaf(p, f, 5.55041087e-2f);
    p = fmaf(p, f, 2.40226507e-1f);
    p = fmaf(p, f, 6.93147180e-1f);
    p = fmaf(p, f, 1.0f);
    float sc = __int_as_float((i + 127) << 23);
    return p * sc;
}
#define EXSCL 0.18033688011f   // 0.125 * log2(e)

// bf16 tiles: 64 elems (128B) per row, 16B-chunk xor swizzle
#define SW(o) ((o) ^ (((o) >> 3) & 0x70))
__device__ __forceinline__ uint32_t swz(uint32_t base, int row, int chunk) {
    return base + row * 128 + (((chunk ^ (row & 7)) & 7) << 4);
}

__device__ __forceinline__ void store_split4(float4 v, char* hb, char* lb, int off) {
    __nv_bfloat162 h0 = __floats2bfloat162_rn(v.x, v.y);
    __nv_bfloat162 h1 = __floats2bfloat162_rn(v.z, v.w);
    float2 f0 = __bfloat1622float2(h0), f1 = __bfloat1622float2(h1);
    __nv_bfloat162 l0 = __floats2bfloat162_rn(v.x - f0.x, v.y - f0.y);
    __nv_bfloat162 l1 = __floats2bfloat162_rn(v.z - f1.x, v.w - f1.y);
    int s0 = SW(off), s1 = SW(off + 4);
    *(uint32_t*)(hb + s0) = reinterpret_cast<uint32_t&>(h0);
    *(uint32_t*)(hb + s1) = reinterpret_cast<uint32_t&>(h1);
    *(uint32_t*)(lb + s0) = reinterpret_cast<uint32_t&>(l0);
    *(uint32_t*)(lb + s1) = reinterpret_cast<uint32_t&>(l1);
}

// ------------------- Kernel A: S=QK^T, exp epilogue, rowsum -------------------
// 64-row q-tiles, double-buffered K stages, register prefetch, direct fragment
// epilogue (no stage). smem: QH 8K | QL 8K | K stages 2x32K | rs 512B
#define S_QH 0
#define S_QL 8192
#define S_KH(s) (16384 + (s)*32768)
#define S_KL(s) (16384 + (s)*32768 + 16384)
#define S_RS 81920
#define S_SZ (S_RS + 768)

__global__ void __launch_bounds__(256) scores_k(
    const float* __restrict__ Q, const float* __restrict__ Kg,
    const int* __restrict__ Mk, const float* __restrict__ P, float* __restrict__ E)
{
    extern __shared__ char sm[];
    const uint32_t sb = smem_u32(sm);
    const int t = threadIdx.x, w = t >> 5, lane = t & 31;
    const int mw = w >> 1, nw = w & 1;     // warp tile: rows mw*16, cols nw*64
    const int bh = blockIdx.y, q0 = blockIdx.x * 64;

    const float* Qb = Q + ((size_t)bh * SEQ + q0) * HD;
    const float* Kb = Kg + (size_t)bh * SEQ * HD;

    // resident Q (64 x 64) split to smem
#pragma unroll
    for (int i = 0; i < 4; i++) {
        int idx = t + i * 256, r = idx >> 4, c = idx & 15;
        store_split4(*(const float4*)(Qb + r * HD + c * 4), sm + S_QH, sm + S_QL, r * 128 + c * 8);
    }

    // prefetch K tile 0 (128 rows x 64 cols)
    const int lr = t >> 4, lc = t & 15;   // lr: row/16grp base, lc: float4 chunk
    float4 kr[8];
#pragma unroll
    for (int i = 0; i < 8; i++)
        kr[i] = *(const float4*)(Kb + (size_t)(lr + i * 16) * HD + lc * 4);

    float rs0 = 0.0f, rs1 = 0.0f;
    const int fr = lane >> 2;              // fragment row within 8
    const int fc = 2 * (lane & 3);         // fragment col pair base

    for (int kt = 0; kt < 16; kt++) {
        const int s = kt & 1;
        // store prefetched K to stage s (split)
#pragma unroll
        for (int i = 0; i < 8; i++)
            store_split4(kr[i], sm + S_KH(s), sm + S_KL(s), (lr + i * 16) * 128 + lc * 8);
        __syncthreads();
        if (kt < 15) {
            const float* Kt = Kb + (size_t)(kt + 1) * 128 * HD;
#pragma unroll
            for (int i = 0; i < 8; i++)
                kr[i] = *(const float4*)(Kt + (size_t)(lr + i * 16) * HD + lc * 4);
        }

        float acc[8][4];
#pragma unroll
        for (int ni = 0; ni < 8; ni++)
#pragma unroll
            for (int j = 0; j < 4; j++) acc[ni][j] = 0.0f;

#pragma unroll
        for (int kc = 0; kc < 4; kc++) {
            uint32_t ah[4], al[4];
            LDSM4(ah, swz(sb + S_QH, mw * 16 + (lane & 15), kc * 2 + (lane >> 4)));
            LDSM4(al, swz(sb + S_QL, mw * 16 + (lane & 15), kc * 2 + (lane >> 4)));
#pragma unroll
            for (int ni = 0; ni < 8; ni++) {
                uint32_t bh2[2], bl2[2];
                const int nb = nw * 64 + ni * 8 + (lane & 7);
                LDSM2(bh2, swz(sb + S_KH(s), nb, kc * 2 + ((lane >> 3) & 1)));
                LDSM2(bl2, swz(sb + S_KL(s), nb, kc * 2 + ((lane >> 3) & 1)));
                mma16816(acc[ni], ah, bh2);
                mma16816(acc[ni], ah, bl2);
                mma16816(acc[ni], al, bh2);
            }
        }

        // direct fragment epilogue: e = mask ? (p+1e-12)*2^(s*c) : 0
        const size_t gr0 = ((size_t)(bh * SEQ + q0 + mw * 16 + fr)) * SEQ;
        const size_t cb  = (size_t)kt * 128 + nw * 64 + fc;
#pragma unroll
        for (int ni = 0; ni < 8; ni++) {
            size_t g0 = gr0 + cb + ni * 8;
            int2   m0 = *(const int2*)  (Mk + g0);
            float2 p0 = *(const float2*)(P + g0);
            float2 e0;
            e0.x = m0.x ? (p0.x + 1e-12f) * fexp2(acc[ni][0] * EXSCL) : 0.0f;
            e0.y = m0.y ? (p0.y + 1e-12f) * fexp2(acc[ni][1] * EXSCL) : 0.0f;
            *(float2*)(E + g0) = e0;
            rs0 += e0.x + e0.y;
            size_t g1 = g0 + 8 * SEQ;
            int2   m1 = *(const int2*)  (Mk + g1);
            float2 p1 = *(const float2*)(P + g1);
            float2 e1;
            e1.x = m1.x ? (p1.x + 1e-12f) * fexp2(acc[ni][2] * EXSCL) : 0.0f;
            e1.y = m1.y ? (p1.y + 1e-12f) * fexp2(acc[ni][3] * EXSCL) : 0.0f;
            *(float2*)(E + g1) = e1;
            rs1 += e1.x + e1.y;
        }
    }

    // rowsum reduction: 4 lanes share a row; combine warp pair via smem
    rs0 += __shfl_xor_sync(0xffffffffu, rs0, 1);
    rs0 += __shfl_xor_sync(0xffffffffu, rs0, 2);
    rs1 += __shfl_xor_sync(0xffffffffu, rs1, 1);
    rs1 += __shfl_xor_sync(0xffffffffu, rs1, 2);
    float* rss = (float*)(sm + S_RS);
    if ((lane & 3) == 0) {
        rss[nw * 64 + mw * 16 + fr]     = rs0;
        rss[nw * 64 + mw * 16 + fr + 8] = rs1;
    }
    __syncthreads();
    if (t < 64) g_rowsum[bh * SEQ + q0 + t] = rss[t] + rss[64 + t];
}

// --------------- Kernel B: normalize E in place + O = p_attn V ---------------
// 64-row q-tiles, double-buffered smem, register prefetch.
#define B_EH(s) ((s)*32768)
#define B_EL(s) ((s)*32768 + 8192)
#define B_VH(s) ((s)*32768 + 16384)
#define B_VL(s) ((s)*32768 + 24576)
#define B_IV 65536
#define B_SZ (B_IV + 256)

__global__ void __launch_bounds__(256) pv_k(
    const float* __restrict__ Vg, float* __restrict__ E, float* __restrict__ O)
{
    extern __shared__ char sm[];
    const uint32_t sb = smem_u32(sm);
    const int t = threadIdx.x, w = t >> 5, lane = t & 31;
    const int mw = w >> 1, nw = w & 1;     // warp tile: rows mw*16, cols nw*32
    const int bh = blockIdx.y, q0 = blockIdx.x * 64;

    float* sinv = (float*)(sm + B_IV);
    if (t < 64) sinv[t] = 1.0f / g_rowsum[bh * SEQ + q0 + t];

    float* Eb = E + ((size_t)bh * SEQ + q0) * SEQ;
    const float* Vb = Vg + (size_t)bh * SEQ * HD;

    const int r_ = t >> 4, c_ = t & 15;

    float4 er[4], vr[4];
#pragma unroll
    for (int i = 0; i < 4; i++) {
        er[i] = *(const float4*)(Eb + (size_t)(r_ + i * 16) * SEQ + c_ * 4);
        vr[i] = *(const float4*)(Vb + (size_t)(r_ + i * 16) * HD + c_ * 4);
    }

    float acc[4][4];
#pragma unroll
    for (int ni = 0; ni < 4; ni++)
#pragma unroll
        for (int j = 0; j < 4; j++) acc[ni][j] = 0.0f;

    __syncthreads();   // sinv visible

    for (int kt = 0; kt < 32; kt++) {
        const int s = kt & 1;
#pragma unroll
        for (int i = 0; i < 4; i++) {
            const int r = r_ + i * 16;
            const float inv = sinv[r];
            float4 v = er[i];
            v.x *= inv; v.y *= inv; v.z *= inv; v.w *= inv;
            *(float4*)(Eb + (size_t)r * SEQ + kt * 64 + c_ * 4) = v;
            store_split4(v, sm + B_EH(s), sm + B_EL(s), r * 128 + c_ * 8);
            store_split4(vr[i], sm + B_VH(s), sm + B_VL(s), r * 128 + c_ * 8);
        }
        __syncthreads();
        if (kt < 31) {
#pragma unroll
            for (int i = 0; i < 4; i++) {
                er[i] = *(const float4*)(Eb + (size_t)(r_ + i * 16) * SEQ + (kt + 1) * 64 + c_ * 4);
                vr[i] = *(const float4*)(Vb + (size_t)((kt + 1) * 64 + r_ + i * 16) * HD + c_ * 4);
            }
        }
#pragma unroll
        for (int kc = 0; kc < 4; kc++) {
            uint32_t bhf[4][2], blf[4][2];
#pragma unroll
            for (int ni = 0; ni < 4; ni++) {
                const int nch = nw * 4 + ni;
                LDSM2T(bhf[ni], swz(sb + B_VH(s), kc * 16 + (lane & 15), nch));
                LDSM2T(blf[ni], swz(sb + B_VL(s), kc * 16 + (lane & 15), nch));
            }
            uint32_t ah[4], al[4];
            LDSM4(ah, swz(sb + B_EH(s), mw * 16 + (lane & 15), kc * 2 + (lane >> 4)));
            LDSM4(al, swz(sb + B_EL(s), mw * 16 + (lane & 15), kc * 2 + (lane >> 4)));
#pragma unroll
            for (int ni = 0; ni < 4; ni++) {
                mma16816(acc[ni], ah, bhf[ni]);
                mma16816(acc[ni], ah, blf[ni]);
                mma16816(acc[ni], al, bhf[ni]);
            }
        }
    }

    const int r0 = mw * 16 + (lane >> 2);
    const int c0 = nw * 32 + 2 * (lane & 3);
#pragma unroll
    for (int ni = 0; ni < 4; ni++) {
        size_t g0 = ((size_t)(bh * SEQ + q0 + r0)) * HD + c0 + ni * 8;
        *(float2*)(O + g0) = make_float2(acc[ni][0], acc[ni][1]);
        *(float2*)(O + g0 + 8 * HD) = make_float2(acc[ni][2], acc[ni][3]);
    }
}

extern "C" void kernel_launch(void* const* d_in, const int* in_sizes, int n_in,
                              void* d_out, int out_size) {
    const float* Q = (const float*)d_in[0];
    const float* K = (const float*)d_in[1];
    const float* V = (const float*)d_in[2];
    const int*   M = (const int*)  d_in[3];
    const float* P = (const float*)d_in[4];
    float* out = (float*)d_out;
    float* E   = out + OUT_ELEMS;

    cudaFuncSetAttribute(scores_k, cudaFuncAttributeMaxDynamicSharedMemorySize, S_SZ);
    cudaFuncSetAttribute(pv_k,     cudaFuncAttributeMaxDynamicSharedMemorySize, B_SZ);

    scores_k<<<dim3(32, 16), 256, S_SZ>>>(Q, K, M, P, E);
    pv_k<<<dim3(32, 16), 256, B_SZ>>>(V, E, out);
}

// round 10
// speedup vs baseline: 2.2856x; 1.0332x over previous
#include <cuda_runtime.h>
#include <cuda_bf16.h>
#include <cstdint>

#define SEQ 2048
#define HD  64
#define OUT_ELEMS (16*SEQ*HD)

__device__ float g_rowsum[16 * SEQ];

// ---------------- helpers ----------------
__device__ __forceinline__ uint32_t smem_u32(const void* p) {
    uint32_t a;
    asm("{ .reg .u64 t; cvta.to.shared.u64 t, %1; cvt.u32.u64 %0, t; }" : "=r"(a) : "l"(p));
    return a;
}

#define LDSM4(r, a) \
    asm volatile("ldmatrix.sync.aligned.m8n8.x4.shared.b16 {%0,%1,%2,%3}, [%4];" \
        : "=r"((r)[0]), "=r"((r)[1]), "=r"((r)[2]), "=r"((r)[3]) : "r"(a))
#define LDSM2(r, a) \
    asm volatile("ldmatrix.sync.aligned.m8n8.x2.shared.b16 {%0,%1}, [%2];" \
        : "=r"((r)[0]), "=r"((r)[1]) : "r"(a))
#define LDSM2T(r, a) \
    asm volatile("ldmatrix.sync.aligned.m8n8.x2.trans.shared.b16 {%0,%1}, [%2];" \
        : "=r"((r)[0]), "=r"((r)[1]) : "r"(a))

__device__ __forceinline__ void mma16816(float* d, const uint32_t* a, const uint32_t* b) {
    asm volatile(
        "mma.sync.aligned.m16n8k16.row.col.f32.bf16.bf16.f32 "
        "{%0,%1,%2,%3}, {%4,%5,%6,%7}, {%8,%9}, {%0,%1,%2,%3};"
        : "+f"(d[0]), "+f"(d[1]), "+f"(d[2]), "+f"(d[3])
        : "r"(a[0]), "r"(a[1]), "r"(a[2]), "r"(a[3]), "r"(b[0]), "r"(b[1]));
}

// fast 2^t : FFMA-only. |t| < 60 assumed.
__device__ __forceinline__ float fexp2(float t) {
    float z = t + 12582912.0f;
    int   i = __float_as_int(z);
    float f = t - (z - 12582912.0f);
    float p =          1.33335581e-3f;
    p = fmaf(p, f, 9.61812910e-3f);
    p = fmaf(p, f, 5.55041087e-2f);
    p = fmaf(p, f, 2.40226507e-1f);
    p = fmaf(p, f, 6.93147180e-1f);
    p = fmaf(p, f, 1.0f);
    float sc = __int_as_float((i + 127) << 23);
    return p * sc;
}
#define EXSCL 0.18033688011f   // 0.125 * log2(e)

// bf16 tiles: 64 elems (128B) per row, 16B-chunk xor swizzle
#define SW(o) ((o) ^ (((o) >> 3) & 0x70))
__device__ __forceinline__ uint32_t swz(uint32_t base, int row, int chunk) {
    return base + row * 128 + (((chunk ^ (row & 7)) & 7) << 4);
}

// split f32x4 -> bf16 hi/lo, stored as 2x STS.64 (swizzle keeps the pair contiguous:
// off % 8 == 0 so SW(off+4) == SW(off)+4)
__device__ __forceinline__ void store_split4(float4 v, char* hb, char* lb, int off) {
    __nv_bfloat162 h0 = __floats2bfloat162_rn(v.x, v.y);
    __nv_bfloat162 h1 = __floats2bfloat162_rn(v.z, v.w);
    float2 f0 = __bfloat1622float2(h0), f1 = __bfloat1622float2(h1);
    __nv_bfloat162 l0 = __floats2bfloat162_rn(v.x - f0.x, v.y - f0.y);
    __nv_bfloat162 l1 = __floats2bfloat162_rn(v.z - f1.x, v.w - f1.y);
    int s0 = SW(off);
    uint2 hp = make_uint2(reinterpret_cast<uint32_t&>(h0), reinterpret_cast<uint32_t&>(h1));
    uint2 lp = make_uint2(reinterpret_cast<uint32_t&>(l0), reinterpret_cast<uint32_t&>(l1));
    *(uint2*)(hb + s0) = hp;
    *(uint2*)(lb + s0) = lp;
}

// ------------------- Kernel A: S=QK^T, exp epilogue, rowsum -------------------
// 64-row q-tiles, double-buffered K stages, register prefetch, direct fragment
// epilogue. smem: QH 8K | QL 8K | K stages 2x32K | rs 512B
#define S_QH 0
#define S_QL 8192
#define S_KH(s) (16384 + (s)*32768)
#define S_KL(s) (16384 + (s)*32768 + 16384)
#define S_RS 81920
#define S_SZ (S_RS + 768)

__global__ void __launch_bounds__(256, 2) scores_k(
    const float* __restrict__ Q, const float* __restrict__ Kg,
    const int* __restrict__ Mk, const float* __restrict__ P, float* __restrict__ E)
{
    extern __shared__ char sm[];
    const uint32_t sb = smem_u32(sm);
    const int t = threadIdx.x, w = t >> 5, lane = t & 31;
    const int mw = w >> 1, nw = w & 1;     // warp tile: rows mw*16, cols nw*64
    const int bh = blockIdx.y, q0 = blockIdx.x * 64;

    const float* Qb = Q + ((size_t)bh * SEQ + q0) * HD;
    const float* Kb = Kg + (size_t)bh * SEQ * HD;

    // resident Q (64 x 64) split to smem
#pragma unroll
    for (int i = 0; i < 4; i++) {
        int idx = t + i * 256, r = idx >> 4, c = idx & 15;
        store_split4(*(const float4*)(Qb + r * HD + c * 4), sm + S_QH, sm + S_QL, r * 128 + c * 8);
    }

    // prefetch K tile 0 (128 rows x 64 cols)
    const int lr = t >> 4, lc = t & 15;
    float4 kr[8];
#pragma unroll
    for (int i = 0; i < 8; i++)
        kr[i] = *(const float4*)(Kb + (size_t)(lr + i * 16) * HD + lc * 4);

    float rs0 = 0.0f, rs1 = 0.0f;
    const int fr = lane >> 2;
    const int fc = 2 * (lane & 3);

    for (int kt = 0; kt < 16; kt++) {
        const int s = kt & 1;
#pragma unroll
        for (int i = 0; i < 8; i++)
            store_split4(kr[i], sm + S_KH(s), sm + S_KL(s), (lr + i * 16) * 128 + lc * 8);
        __syncthreads();
        if (kt < 15) {
            const float* Kt = Kb + (size_t)(kt + 1) * 128 * HD;
#pragma unroll
            for (int i = 0; i < 8; i++)
                kr[i] = *(const float4*)(Kt + (size_t)(lr + i * 16) * HD + lc * 4);
        }

        float acc[8][4];
#pragma unroll
        for (int ni = 0; ni < 8; ni++)
#pragma unroll
            for (int j = 0; j < 4; j++) acc[ni][j] = 0.0f;

#pragma unroll
        for (int kc = 0; kc < 4; kc++) {
            uint32_t ah[4], al[4];
            LDSM4(ah, swz(sb + S_QH, mw * 16 + (lane & 15), kc * 2 + (lane >> 4)));
            LDSM4(al, swz(sb + S_QL, mw * 16 + (lane & 15), kc * 2 + (lane >> 4)));
#pragma unroll
            for (int ni = 0; ni < 8; ni++) {
                uint32_t bh2[2], bl2[2];
                const int nb = nw * 64 + ni * 8 + (lane & 7);
                LDSM2(bh2, swz(sb + S_KH(s), nb, kc * 2 + ((lane >> 3) & 1)));
                LDSM2(bl2, swz(sb + S_KL(s), nb, kc * 2 + ((lane >> 3) & 1)));
                mma16816(acc[ni], ah, bh2);
                mma16816(acc[ni], ah, bl2);
                mma16816(acc[ni], al, bh2);
            }
        }

        // direct fragment epilogue: e = mask ? (p+1e-12)*2^(s*c) : 0
        const size_t gr0 = ((size_t)(bh * SEQ + q0 + mw * 16 + fr)) * SEQ;
        const size_t cb  = (size_t)kt * 128 + nw * 64 + fc;
#pragma unroll
        for (int ni = 0; ni < 8; ni++) {
            size_t g0 = gr0 + cb + ni * 8;
            int2   m0 = *(const int2*)  (Mk + g0);
            float2 p0 = *(const float2*)(P + g0);
            float2 e0;
            e0.x = m0.x ? (p0.x + 1e-12f) * fexp2(acc[ni][0] * EXSCL) : 0.0f;
            e0.y = m0.y ? (p0.y + 1e-12f) * fexp2(acc[ni][1] * EXSCL) : 0.0f;
            *(float2*)(E + g0) = e0;
            rs0 += e0.x + e0.y;
            size_t g1 = g0 + 8 * SEQ;
            int2   m1 = *(const int2*)  (Mk + g1);
            float2 p1 = *(const float2*)(P + g1);
            float2 e1;
            e1.x = m1.x ? (p1.x + 1e-12f) * fexp2(acc[ni][2] * EXSCL) : 0.0f;
            e1.y = m1.y ? (p1.y + 1e-12f) * fexp2(acc[ni][3] * EXSCL) : 0.0f;
            *(float2*)(E + g1) = e1;
            rs1 += e1.x + e1.y;
        }
    }

    rs0 += __shfl_xor_sync(0xffffffffu, rs0, 1);
    rs0 += __shfl_xor_sync(0xffffffffu, rs0, 2);
    rs1 += __shfl_xor_sync(0xffffffffu, rs1, 1);
    rs1 += __shfl_xor_sync(0xffffffffu, rs1, 2);
    float* rss = (float*)(sm + S_RS);
    if ((lane & 3) == 0) {
        rss[nw * 64 + mw * 16 + fr]     = rs0;
        rss[nw * 64 + mw * 16 + fr + 8] = rs1;
    }
    __syncthreads();
    if (t < 64) g_rowsum[bh * SEQ + q0 + t] = rss[t] + rss[64 + t];
}

// --------------- Kernel B: normalize E in place + O = p_attn V ---------------
#define B_EH(s) ((s)*32768)
#define B_EL(s) ((s)*32768 + 8192)
#define B_VH(s) ((s)*32768 + 16384)
#define B_VL(s) ((s)*32768 + 24576)
#define B_IV 65536
#define B_SZ (B_IV + 256)

__global__ void __launch_bounds__(256, 2) pv_k(
    const float* __restrict__ Vg, float* __restrict__ E, float* __restrict__ O)
{
    extern __shared__ char sm[];
    const uint32_t sb = smem_u32(sm);
    const int t = threadIdx.x, w = t >> 5, lane = t & 31;
    const int mw = w >> 1, nw = w & 1;
    const int bh = blockIdx.y, q0 = blockIdx.x * 64;

    float* sinv = (float*)(sm + B_IV);
    if (t < 64) sinv[t] = 1.0f / g_rowsum[bh * SEQ + q0 + t];

    float* Eb = E + ((size_t)bh * SEQ + q0) * SEQ;
    const float* Vb = Vg + (size_t)bh * SEQ * HD;

    const int r_ = t >> 4, c_ = t & 15;

    float4 er[4], vr[4];
#pragma unroll
    for (int i = 0; i < 4; i++) {
        er[i] = *(const float4*)(Eb + (size_t)(r_ + i * 16) * SEQ + c_ * 4);
        vr[i] = *(const float4*)(Vb + (size_t)(r_ + i * 16) * HD + c_ * 4);
    }

    float acc[4][4];
#pragma unroll
    for (int ni = 0; ni < 4; ni++)
#pragma unroll
        for (int j = 0; j < 4; j++) acc[ni][j] = 0.0f;

    __syncthreads();

    for (int kt = 0; kt < 32; kt++) {
        const int s = kt & 1;
#pragma unroll
        for (int i = 0; i < 4; i++) {
            const int r = r_ + i * 16;
            const float inv = sinv[r];
            float4 v = er[i];
            v.x *= inv; v.y *= inv; v.z *= inv; v.w *= inv;
            *(float4*)(Eb + (size_t)r * SEQ + kt * 64 + c_ * 4) = v;
            store_split4(v, sm + B_EH(s), sm + B_EL(s), r * 128 + c_ * 8);
            store_split4(vr[i], sm + B_VH(s), sm + B_VL(s), r * 128 + c_ * 8);
        }
        __syncthreads();
        if (kt < 31) {
#pragma unroll
            for (int i = 0; i < 4; i++) {
                er[i] = *(const float4*)(Eb + (size_t)(r_ + i * 16) * SEQ + (kt + 1) * 64 + c_ * 4);
                vr[i] = *(const float4*)(Vb + (size_t)((kt + 1) * 64 + r_ + i * 16) * HD + c_ * 4);
            }
        }
#pragma unroll
        for (int kc = 0; kc < 4; kc++) {
            uint32_t bhf[4][2], blf[4][2];
#pragma unroll
            for (int ni = 0; ni < 4; ni++) {
                const int nch = nw * 4 + ni;
                LDSM2T(bhf[ni], swz(sb + B_VH(s), kc * 16 + (lane & 15), nch));
                LDSM2T(blf[ni], swz(sb + B_VL(s), kc * 16 + (lane & 15), nch));
            }
            uint32_t ah[4], al[4];
            LDSM4(ah, swz(sb + B_EH(s), mw * 16 + (lane & 15), kc * 2 + (lane >> 4)));
            LDSM4(al, swz(sb + B_EL(s), mw * 16 + (lane & 15), kc * 2 + (lane >> 4)));
#pragma unroll
            for (int ni = 0; ni < 4; ni++) {
                mma16816(acc[ni], ah, bhf[ni]);
                mma16816(acc[ni], ah, blf[ni]);
                mma16816(acc[ni], al, bhf[ni]);
            }
        }
    }

    const int r0 = mw * 16 + (lane >> 2);
    const int c0 = nw * 32 + 2 * (lane & 3);
#pragma unroll
    for (int ni = 0; ni < 4; ni++) {
        size_t g0 = ((size_t)(bh * SEQ + q0 + r0)) * HD + c0 + ni * 8;
        *(float2*)(O + g0) = make_float2(acc[ni][0], acc[ni][1]);
        *(float2*)(O + g0 + 8 * HD) = make_float2(acc[ni][2], acc[ni][3]);
    }
}

extern "C" void kernel_launch(void* const* d_in, const int* in_sizes, int n_in,
                              void* d_out, int out_size) {
    const float* Q = (const float*)d_in[0];
    const float* K = (const float*)d_in[1];
    const float* V = (const float*)d_in[2];
    const int*   M = (const int*)  d_in[3];
    const float* P = (const float*)d_in[4];
    float* out = (float*)d_out;
    float* E   = out + OUT_ELEMS;

    cudaFuncSetAttribute(scores_k, cudaFuncAttributeMaxDynamicSharedMemorySize, S_SZ);
    cudaFuncSetAttribute(pv_k,     cudaFuncAttributeMaxDynamicSharedMemorySize, B_SZ);

    scores_k<<<dim3(32, 16), 256, S_SZ>>>(Q, K, M, P, E);
    pv_k<<<dim3(32, 16), 256, B_SZ>>>(V, E, out);
}